// round 7
// baseline (speedup 1.0000x reference)
#include <cuda_runtime.h>

#define S 2048
#define D 64
#define BH 32
#define SCALE 0.125f   // 1/sqrt(64)

// ---------------------------------------------------------------------------
// K1: raw masked scores  attn[bh, q, k] = (q . k) / 8  for k<=q, else 0
// Tile: 128 (q) x 64 (k), 256 threads, 8x4 per thread, D chunked by 32.
// ---------------------------------------------------------------------------
__global__ __launch_bounds__(256) void k_scores(const float* __restrict__ qg,
                                                const float* __restrict__ kg,
                                                float* __restrict__ attn)
{
    const int kt = blockIdx.x;          // 0..31  (k in 64-wide tiles)
    const int qt = blockIdx.y;          // 0..15  (q in 128-wide tiles)
    const int bh = blockIdx.z;          // 0..31
    const int q0 = qt * 128;
    const int k0 = kt * 64;

    float* __restrict__ ab = attn + (size_t)bh * S * S;
    const int tid = threadIdx.x;

    // Tiles entirely above the diagonal: write zeros, done.
    if (k0 > q0 + 127) {
        const float4 z = make_float4(0.f, 0.f, 0.f, 0.f);
        #pragma unroll
        for (int i = 0; i < 8; i++) {
            int f4  = tid + i * 256;          // 2048 float4s = 128x64 floats
            int row = f4 >> 4;                // 16 float4 per 64-col row
            int c4  = f4 & 15;
            *reinterpret_cast<float4*>(&ab[(size_t)(q0 + row) * S + k0 + c4 * 4]) = z;
        }
        return;
    }

    const float* __restrict__ qb = qg + (size_t)bh * S * D;
    const float* __restrict__ kb = kg + (size_t)bh * S * D;

    __shared__ float Qs[128][33];   // pad 33: conflict-free a-loads
    __shared__ float Ks[64][33];    // pad 33 + interleaved c-map: conflict-free b-loads

    const int tx = tid & 15;        // 0..15 -> cols c = tx + 16*j
    const int ty = tid >> 4;        // 0..15 -> rows r = 8*ty + i
    const int r0 = ty * 8;

    float acc[8][4];
    #pragma unroll
    for (int i = 0; i < 8; i++)
        #pragma unroll
        for (int j = 0; j < 4; j++) acc[i][j] = 0.f;

    #pragma unroll
    for (int dc = 0; dc < 2; dc++) {
        const int d0 = dc * 32;
        // load Q tile: 128 x 32  (1024 float4, 4 per thread), scalar STS (padded rows)
        #pragma unroll
        for (int i = 0; i < 4; i++) {
            int f4  = tid + i * 256;
            int row = f4 >> 3;              // 8 float4 per 32-col row
            int d4  = (f4 & 7) * 4;
            float4 v = *reinterpret_cast<const float4*>(&qb[(size_t)(q0 + row) * D + d0 + d4]);
            Qs[row][d4 + 0] = v.x; Qs[row][d4 + 1] = v.y;
            Qs[row][d4 + 2] = v.z; Qs[row][d4 + 3] = v.w;
        }
        // load K tile: 64 x 32  (512 float4, 2 per thread)
        #pragma unroll
        for (int i = 0; i < 2; i++) {
            int f4  = tid + i * 256;
            int row = f4 >> 3;
            int d4  = (f4 & 7) * 4;
            float4 v = *reinterpret_cast<const float4*>(&kb[(size_t)(k0 + row) * D + d0 + d4]);
            Ks[row][d4 + 0] = v.x; Ks[row][d4 + 1] = v.y;
            Ks[row][d4 + 2] = v.z; Ks[row][d4 + 3] = v.w;
        }
        __syncthreads();

        #pragma unroll 8
        for (int kk = 0; kk < 32; kk++) {
            float a[8], b[4];
            #pragma unroll
            for (int i = 0; i < 8; i++) a[i] = Qs[r0 + i][kk];
            #pragma unroll
            for (int j = 0; j < 4; j++) b[j] = Ks[tx + 16 * j][kk];
            #pragma unroll
            for (int i = 0; i < 8; i++)
                #pragma unroll
                for (int j = 0; j < 4; j++)
                    acc[i][j] = fmaf(a[i], b[j], acc[i][j]);
        }
        __syncthreads();
    }

    // write raw scores with causal mask (masked = 0.0)
    #pragma unroll
    for (int i = 0; i < 8; i++) {
        const int gq = q0 + r0 + i;
        #pragma unroll
        for (int j = 0; j < 4; j++) {
            const int gk = k0 + tx + 16 * j;
            ab[(size_t)gq * S + gk] = (gk <= gq) ? acc[i][j] * SCALE : 0.f;
        }
    }
}

// ---------------------------------------------------------------------------
// K2: in-place row softmax over attn[bh, q, 0..q]  (entries > q stay 0)
// One block (128 threads) per row; row cached in smem.
// ---------------------------------------------------------------------------
__global__ __launch_bounds__(128) void k_softmax(float* __restrict__ attn)
{
    const int row = blockIdx.x;            // 0..65535
    const int bh  = row >> 11;
    const int qy  = row & 2047;
    float* __restrict__ a = attn + (size_t)bh * S * S + (size_t)qy * S;
    const int len = qy + 1;

    __shared__ float buf[2048];
    __shared__ float red[4];
    const int tid  = threadIdx.x;
    const int lane = tid & 31;
    const int wrp  = tid >> 5;

    float m = -1e30f;
    for (int i = tid; i < len; i += 128) {
        float v = a[i];
        buf[i] = v;
        m = fmaxf(m, v);
    }
    #pragma unroll
    for (int o = 16; o; o >>= 1) m = fmaxf(m, __shfl_xor_sync(0xffffffffu, m, o));
    if (lane == 0) red[wrp] = m;
    __syncthreads();
    m = fmaxf(fmaxf(red[0], red[1]), fmaxf(red[2], red[3]));

    float s = 0.f;
    for (int i = tid; i < len; i += 128) {
        float e = __expf(buf[i] - m);
        buf[i] = e;
        s += e;
    }
    #pragma unroll
    for (int o = 16; o; o >>= 1) s += __shfl_xor_sync(0xffffffffu, s, o);
    __syncthreads();                        // everyone done reading red for max
    if (lane == 0) red[wrp] = s;
    __syncthreads();
    s = red[0] + red[1] + red[2] + red[3];
    const float inv = 1.f / s;

    for (int i = tid; i < len; i += 128) a[i] = buf[i] * inv;
}

// ---------------------------------------------------------------------------
// K3: out[bh, q, d] = sum_k attn[bh, q, k] * v[bh, k, d]
// Tile: 128 (q) x 64 (d), 256 threads, 8x4 per thread, k chunked by 32.
// attn zeros above the diagonal make the diagonal tile mask-free.
// ---------------------------------------------------------------------------
__global__ __launch_bounds__(256) void k_av(const float* __restrict__ attn,
                                            const float* __restrict__ vg,
                                            float* __restrict__ outg)
{
    const int qt = 15 - (int)blockIdx.x;   // descending work order for balance
    const int bh = blockIdx.y;
    const int q0 = qt * 128;

    const float* __restrict__ ab = attn + (size_t)bh * S * S;
    const float* __restrict__ vb = vg   + (size_t)bh * S * D;
    float* __restrict__ ob       = outg + (size_t)bh * S * D;

    __shared__ float As[128][33];   // pad: conflict-free a-loads
    __shared__ float Vs[32][64];    // natural layout: conflict-free float4 b-loads

    const int tid = threadIdx.x;
    const int tx  = tid & 15;       // cols c0 = 4*tx (float4)
    const int ty  = tid >> 4;       // rows r0 = 8*ty
    const int r0  = ty * 8;
    const int c0  = tx * 4;

    float acc[8][4];
    #pragma unroll
    for (int i = 0; i < 8; i++)
        #pragma unroll
        for (int j = 0; j < 4; j++) acc[i][j] = 0.f;

    const int nch = (qt + 1) * 4;   // 32-wide k-chunks covering k <= q0+127

    for (int ch = 0; ch < nch; ch++) {
        const int kb = ch * 32;
        // load attn tile 128 x 32 (1024 float4, 4 per thread), scalar STS
        #pragma unroll
        for (int i = 0; i < 4; i++) {
            int f4  = tid + i * 256;
            int row = f4 >> 3;
            int k4  = (f4 & 7) * 4;
            float4 v = *reinterpret_cast<const float4*>(&ab[(size_t)(q0 + row) * S + kb + k4]);
            As[row][k4 + 0] = v.x; As[row][k4 + 1] = v.y;
            As[row][k4 + 2] = v.z; As[row][k4 + 3] = v.w;
        }
        // load V tile 32 x 64 (512 float4, 2 per thread), float4 STS
        #pragma unroll
        for (int i = 0; i < 2; i++) {
            int f4  = tid + i * 256;
            int row = f4 >> 4;              // 16 float4 per 64-col row
            int c4  = (f4 & 15) * 4;
            float4 v = *reinterpret_cast<const float4*>(&vb[(size_t)(kb + row) * D + c4]);
            *reinterpret_cast<float4*>(&Vs[row][c4]) = v;
        }
        __syncthreads();

        #pragma unroll 8
        for (int kk = 0; kk < 32; kk++) {
            float a[8];
            #pragma unroll
            for (int i = 0; i < 8; i++) a[i] = As[r0 + i][kk];
            float4 b = *reinterpret_cast<const float4*>(&Vs[kk][c0]);
            #pragma unroll
            for (int i = 0; i < 8; i++) {
                acc[i][0] = fmaf(a[i], b.x, acc[i][0]);
                acc[i][1] = fmaf(a[i], b.y, acc[i][1]);
                acc[i][2] = fmaf(a[i], b.z, acc[i][2]);
                acc[i][3] = fmaf(a[i], b.w, acc[i][3]);
            }
        }
        __syncthreads();
    }

    #pragma unroll
    for (int i = 0; i < 8; i++) {
        float4 o = make_float4(acc[i][0], acc[i][1], acc[i][2], acc[i][3]);
        *reinterpret_cast<float4*>(&ob[(size_t)(q0 + r0 + i) * D + c0]) = o;
    }
}

// ---------------------------------------------------------------------------
// launch: d_in = { q, k, v, mask } ; d_out = [ out (B*H*S*D) | attn (B*H*S*S) ]
// ---------------------------------------------------------------------------
extern "C" void kernel_launch(void* const* d_in, const int* in_sizes, int n_in,
                              void* d_out, int out_size)
{
    const float* q = (const float*)d_in[0];
    const float* k = (const float*)d_in[1];
    const float* v = (const float*)d_in[2];
    // d_in[3] = mask (unused: causal mask is structural)

    float* out  = (float*)d_out;
    float* attn = out + (size_t)BH * S * D;   // tuple order: (out, attn)

    k_scores <<<dim3(32, 16, BH), 256>>>(q, k, attn);
    k_softmax<<<BH * S, 128>>>(attn);
    k_av     <<<dim3(16, BH), 256>>>(attn, v, out);
}